// round 11
// baseline (speedup 1.0000x reference)
#include <cuda_runtime.h>

// Problem constants (fixed by the reference).
#define TT   1024
#define BB   16384
#define CH   32          // steps per chunk
#define SQ   5           // log2(CH) squarings for Wx^CH
#define NCH  (TT / CH)   // 32 chunks
#define HB   (BB / 2)    // half-batch offset (pair partner)
#define QB   (BB / 4)    // quarter-batch offset (second pair)

typedef unsigned long long u64;

static_assert((1 << SQ) == CH, "SQ must be log2(CH)");
static_assert(TT % CH == 0, "");

// Scratch.
__device__ float g_part[NCH * 6 * BB];   // zero-state per-chunk db partials
__device__ float g_ckpt[NCH * 6 * BB];   // true db at chunk entry
__device__ float g_m[CH * 6];            // m_s = Wx^s * Wu
__device__ float g_MC[36];               // Wx^CH

// Duplicated-pair weight table, staged by kP then copied to constant bank.
// Layout (u64 units):
//   rows i=0..5 at i*8: [Wx i0..i5 (pairs), Wu i (pair), pad]   (cw[7] = b2 pair)
//   rows j=0..19 at 48+j*16: [W1 j0..j11 (pairs), b1 j, W2 j, pad, pad]
#define CW_N 368
#define SW_ROWJ(j) (48 + (j) * 16)
__device__ u64 g_wdup[CW_N];
__constant__ __align__(16) u64 cw[CW_N];

// ---- f32x2 helpers (sm_100+ packed fp32 pipe) ----
__device__ __forceinline__ u64 pack2(float lo, float hi) {
    u64 r; asm("mov.b64 %0,{%1,%2};" : "=l"(r) : "f"(lo), "f"(hi)); return r;
}
__device__ __forceinline__ void unpack2(u64 v, float& lo, float& hi) {
    asm("mov.b64 {%0,%1},%2;" : "=f"(lo), "=f"(hi) : "l"(v));
}
__device__ __forceinline__ u64 fma2(u64 a, u64 b, u64 c) {
    u64 d; asm("fma.rn.f32x2 %0,%1,%2,%3;" : "=l"(d) : "l"(a), "l"(b), "l"(c)); return d;
}
__device__ __forceinline__ u64 mul2(u64 a, u64 b) {
    u64 d; asm("mul.rn.f32x2 %0,%1,%2;" : "=l"(d) : "l"(a), "l"(b)); return d;
}
__device__ __forceinline__ float tanh_(float x) {
    float y; asm("tanh.approx.f32 %0,%1;" : "=f"(y) : "f"(x)); return y;
}

// ============================================================
// Kernel P: precompute m_s = Wx^s Wu, Wx^CH, and the duplicated
// weight-pair table g_wdup. One block of 64 threads.
// ============================================================
__global__ void __launch_bounds__(64) kP(const float* __restrict__ Wx,
                                         const float* __restrict__ Wu,
                                         const float* __restrict__ W1,
                                         const float* __restrict__ b1,
                                         const float* __restrict__ W2,
                                         const float* __restrict__ b2) {
    __shared__ float sM[36], sm[6], sP[36], st[36];
    int t = threadIdx.x;
    if (t < 36) sM[t] = Wx[t];
    if (t < 6)  sm[t] = Wu[t];
    __syncthreads();

    for (int s = 0; s < CH; s++) {
        if (t < 6) g_m[s * 6 + t] = sm[t];
        __syncthreads();
        float nv = 0.f;
        if (t < 6) {
#pragma unroll
            for (int k = 0; k < 6; k++) nv = fmaf(sM[t * 6 + k], sm[k], nv);
        }
        __syncthreads();
        if (t < 6) sm[t] = nv;
        __syncthreads();
    }

    if (t < 36) sP[t] = sM[t];
    __syncthreads();
    for (int p = 0; p < SQ; p++) {
        if (t < 36) {
            int i = t / 6, j = t % 6;
            float a = 0.f;
#pragma unroll
            for (int k = 0; k < 6; k++) a = fmaf(sP[i * 6 + k], sP[k * 6 + j], a);
            st[t] = a;
        }
        __syncthreads();
        if (t < 36) sP[t] = st[t];
        __syncthreads();
    }
    if (t < 36) g_MC[t] = sP[t];

    // ---- duplicated-pair weight table ----
    if (t < 36) {
        float w = Wx[t];
        g_wdup[(t / 6) * 8 + (t % 6)] = pack2(w, w);
    } else if (t < 42) {
        int i = t - 36;
        float w = Wu[i];
        g_wdup[i * 8 + 6] = pack2(w, w);
        if (i > 0) g_wdup[i * 8 + 7] = 0ull;
    } else if (t < 62) {
        int j = t - 42;
        for (int i = 0; i < 12; i++) {
            float w = W1[j * 12 + i];
            g_wdup[SW_ROWJ(j) + i] = pack2(w, w);
        }
        float bj = b1[j];
        g_wdup[SW_ROWJ(j) + 12] = pack2(bj, bj);
        float w2j = W2[j];
        g_wdup[SW_ROWJ(j) + 13] = pack2(w2j, w2j);
        g_wdup[SW_ROWJ(j) + 14] = 0ull;
        g_wdup[SW_ROWJ(j) + 15] = 0ull;
    } else if (t == 62) {
        float bv = b2[0];
        g_wdup[7] = pack2(bv, bv);   // b2 pair in row-0 pad slot
    }
}

// ============================================================
// Kernel A: per-chunk zero-state db partials via convolution.
// ============================================================
__global__ void __launch_bounds__(256) kA(const float* __restrict__ targets) {
    __shared__ float sm[CH * 6];
    int tid = threadIdx.x;
    for (int i = tid; i < CH * 6; i += 256) sm[i] = g_m[i];
    __syncthreads();

    int b = blockIdx.x * 256 + tid;
    int c = blockIdx.y;
    int t0 = c * CH;

    float acc[6] = {0.f, 0.f, 0.f, 0.f, 0.f, 0.f};
#pragma unroll 8
    for (int s = 0; s < CH; s++) {
        int t = t0 + s;
        float u = 0.f;
        if (t > 0) u = targets[(size_t)(t - 1) * BB + b];
        const float* mm = &sm[(CH - 1 - s) * 6];
#pragma unroll
        for (int i = 0; i < 6; i++) acc[i] = fmaf(mm[i], u, acc[i]);
    }
#pragma unroll
    for (int i = 0; i < 6; i++)
        g_part[((size_t)c * 6 + i) * BB + b] = acc[i];
}

// ============================================================
// Kernel B: scan across chunks: db_in(c+1) = Wx^CH * db_in(c) + partial(c).
// ============================================================
__global__ void __launch_bounds__(256) kB() {
    __shared__ float sM[36];
    int tid = threadIdx.x;
    if (tid < 36) sM[tid] = g_MC[tid];
    __syncthreads();

    int b = blockIdx.x * 256 + tid;
    float v[6] = {0.f, 0.f, 0.f, 0.f, 0.f, 0.f};
#pragma unroll 1
    for (int c = 0; c < NCH; c++) {
#pragma unroll
        for (int i = 0; i < 6; i++)
            g_ckpt[((size_t)c * 6 + i) * BB + b] = v[i];
        float pr[6];
#pragma unroll
        for (int i = 0; i < 6; i++)
            pr[i] = g_part[((size_t)c * 6 + i) * BB + b];
        float nv[6];
#pragma unroll
        for (int i = 0; i < 6; i++) {
            float a = pr[i];
#pragma unroll
            for (int j = 0; j < 6; j++) a = fmaf(sM[i * 6 + j], v[j], a);
            nv[i] = a;
        }
#pragma unroll
        for (int i = 0; i < 6; i++) v[i] = nv[i];
    }
}

// ============================================================
// Kernel C: fused MLP. Weights from the constant bank (warp-uniform
// LDCU -> UR operands). FOUR batch elements per thread, as two f32x2
// pairs (lanes at p, p+HB and p+QB, p+QB+HB): the per-step weight LDCU
// traffic is amortized over 2x the math, cutting issue slots/element
// ~22%. ILP: 8 concurrent MLP chains (4 rows x 2 pairs).
// ============================================================
__global__ void __launch_bounds__(128, 4) kC(const float* __restrict__ inputs,
                                             const float* __restrict__ targets,
                                             float* __restrict__ out) {
    const int tid = threadIdx.x;
    const int c   = blockIdx.y;
    const int p   = blockIdx.x * 128 + tid;   // 0..QB-1

    // nA/nB: [0..5] = db (live state), [6..11] = packed x of current step
    u64 nA[12], nB[12];
    {
        const char* ck = (const char*)g_ckpt + ((size_t)c * 6 * BB + p) * 4;
#pragma unroll
        for (int i = 0; i < 6; i++) {
            const char* r = ck + (size_t)i * BB * 4;
            nA[i] = pack2(*(const float*)(r),
                          *(const float*)(r + (size_t)HB * 4));
            nB[i] = pack2(*(const float*)(r + (size_t)QB * 4),
                          *(const float*)(r + (size_t)(QB + HB) * 4));
        }
    }

    // incremental byte pointers; partner elements via compile-time imm offsets
    const char* xp = (const char*)inputs  + ((size_t)c * CH * BB + p) * 24;
    const char* tp = (const char*)targets + ((size_t)(c * CH - 1) * BB + p) * 4;
    char*       op = (char*)out           + ((size_t)c * CH * BB + p) * 4;

    const float b2v = ((const float*)cw)[14];   // low half of cw[7]

#pragma unroll 1
    for (int s = 0; s < CH; s++) {
        // ---- loads for this step (4 elements x 3 float2) ----
        float2 xa0 = ((const float2*)(xp))[0];
        float2 xb0 = ((const float2*)(xp))[1];
        float2 xc0 = ((const float2*)(xp))[2];
        float2 xa1 = ((const float2*)(xp + (size_t)HB * 24))[0];
        float2 xb1 = ((const float2*)(xp + (size_t)HB * 24))[1];
        float2 xc1 = ((const float2*)(xp + (size_t)HB * 24))[2];
        float2 xa2 = ((const float2*)(xp + (size_t)QB * 24))[0];
        float2 xb2 = ((const float2*)(xp + (size_t)QB * 24))[1];
        float2 xc2 = ((const float2*)(xp + (size_t)QB * 24))[2];
        float2 xa3 = ((const float2*)(xp + (size_t)(QB + HB) * 24))[0];
        float2 xb3 = ((const float2*)(xp + (size_t)(QB + HB) * 24))[1];
        float2 xc3 = ((const float2*)(xp + (size_t)(QB + HB) * 24))[2];
        xp += (size_t)BB * 24;

        float u0 = 0.f, u1 = 0.f, u2 = 0.f, u3 = 0.f;
        if (c + s > 0) {                  // global step t = c*CH+s > 0
            u0 = *(const float*)(tp);
            u1 = *(const float*)(tp + (size_t)HB * 4);
            u2 = *(const float*)(tp + (size_t)QB * 4);
            u3 = *(const float*)(tp + (size_t)(QB + HB) * 4);
        }
        tp += (size_t)BB * 4;
        u64 uA = pack2(u0, u1);
        u64 uB = pack2(u2, u3);

        // ---- db recurrence for both pairs (interleaved chains) ----
        u64 dA[6], dB[6];
#pragma unroll
        for (int i = 0; i < 6; i++) {
            const u64* r = &cw[i * 8];
            u64 a = mul2(r[6], uA);
            u64 b = mul2(r[6], uB);
            a = fma2(r[0], nA[0], a);  b = fma2(r[0], nB[0], b);
            a = fma2(r[1], nA[1], a);  b = fma2(r[1], nB[1], b);
            a = fma2(r[2], nA[2], a);  b = fma2(r[2], nB[2], b);
            a = fma2(r[3], nA[3], a);  b = fma2(r[3], nB[3], b);
            a = fma2(r[4], nA[4], a);  b = fma2(r[4], nB[4], b);
            a = fma2(r[5], nA[5], a);  b = fma2(r[5], nB[5], b);
            dA[i] = a;  dB[i] = b;
        }
#pragma unroll
        for (int i = 0; i < 6; i++) { nA[i] = dA[i]; nB[i] = dB[i]; }
        nA[6]  = pack2(xa0.x, xa1.x);  nB[6]  = pack2(xa2.x, xa3.x);
        nA[7]  = pack2(xa0.y, xa1.y);  nB[7]  = pack2(xa2.y, xa3.y);
        nA[8]  = pack2(xb0.x, xb1.x);  nB[8]  = pack2(xb2.x, xb3.x);
        nA[9]  = pack2(xb0.y, xb1.y);  nB[9]  = pack2(xb2.y, xb3.y);
        nA[10] = pack2(xc0.x, xc1.x);  nB[10] = pack2(xc2.x, xc3.x);
        nA[11] = pack2(xc0.y, xc1.y);  nB[11] = pack2(xc2.y, xc3.y);

        // ---- MLP: 20 hidden rows, 4 rows x 2 pairs = 8 concurrent chains ----
        float o0 = b2v, o1 = b2v, o2 = b2v, o3 = b2v;
#pragma unroll
        for (int jg = 0; jg < 5; jg++) {
            const int j0 = jg * 4;
            u64 a0 = cw[SW_ROWJ(j0 + 0) + 12], b0 = a0;
            u64 a1 = cw[SW_ROWJ(j0 + 1) + 12], b1 = a1;
            u64 a2 = cw[SW_ROWJ(j0 + 2) + 12], b2 = a2;
            u64 a3 = cw[SW_ROWJ(j0 + 3) + 12], b3 = a3;
#pragma unroll
            for (int k = 0; k < 12; k++) {
                u64 w0 = cw[SW_ROWJ(j0 + 0) + k];
                u64 w1 = cw[SW_ROWJ(j0 + 1) + k];
                u64 w2 = cw[SW_ROWJ(j0 + 2) + k];
                u64 w3 = cw[SW_ROWJ(j0 + 3) + k];
                a0 = fma2(w0, nA[k], a0);  b0 = fma2(w0, nB[k], b0);
                a1 = fma2(w1, nA[k], a1);  b1 = fma2(w1, nB[k], b1);
                a2 = fma2(w2, nA[k], a2);  b2 = fma2(w2, nB[k], b2);
                a3 = fma2(w3, nA[k], a3);  b3 = fma2(w3, nB[k], b3);
            }
            float lo, hi, w2s;
            w2s = ((const float*)cw)[(SW_ROWJ(j0 + 0) + 13) * 2];
            unpack2(a0, lo, hi); o0 = fmaf(w2s, tanh_(lo), o0); o1 = fmaf(w2s, tanh_(hi), o1);
            unpack2(b0, lo, hi); o2 = fmaf(w2s, tanh_(lo), o2); o3 = fmaf(w2s, tanh_(hi), o3);
            w2s = ((const float*)cw)[(SW_ROWJ(j0 + 1) + 13) * 2];
            unpack2(a1, lo, hi); o0 = fmaf(w2s, tanh_(lo), o0); o1 = fmaf(w2s, tanh_(hi), o1);
            unpack2(b1, lo, hi); o2 = fmaf(w2s, tanh_(lo), o2); o3 = fmaf(w2s, tanh_(hi), o3);
            w2s = ((const float*)cw)[(SW_ROWJ(j0 + 2) + 13) * 2];
            unpack2(a2, lo, hi); o0 = fmaf(w2s, tanh_(lo), o0); o1 = fmaf(w2s, tanh_(hi), o1);
            unpack2(b2, lo, hi); o2 = fmaf(w2s, tanh_(lo), o2); o3 = fmaf(w2s, tanh_(hi), o3);
            w2s = ((const float*)cw)[(SW_ROWJ(j0 + 3) + 13) * 2];
            unpack2(a3, lo, hi); o0 = fmaf(w2s, tanh_(lo), o0); o1 = fmaf(w2s, tanh_(hi), o1);
            unpack2(b3, lo, hi); o2 = fmaf(w2s, tanh_(lo), o2); o3 = fmaf(w2s, tanh_(hi), o3);
        }

        // ---- stores (4 elements) ----
        *(float*)(op)                            = o0;
        *(float*)(op + (size_t)HB * 4)           = o1;
        *(float*)(op + (size_t)QB * 4)           = o2;
        *(float*)(op + (size_t)(QB + HB) * 4)    = o3;
        op += (size_t)BB * 4;
    }
}

// ============================================================
extern "C" void kernel_launch(void* const* d_in, const int* in_sizes, int n_in,
                              void* d_out, int out_size) {
    (void)in_sizes; (void)n_in; (void)out_size;
    const float* inputs  = (const float*)d_in[0];
    const float* targets = (const float*)d_in[1];
    const float* Wx      = (const float*)d_in[2];
    const float* Wu      = (const float*)d_in[3];
    const float* W1      = (const float*)d_in[4];
    const float* b1      = (const float*)d_in[5];
    const float* W2      = (const float*)d_in[6];
    const float* b2      = (const float*)d_in[7];
    float* out = (float*)d_out;

    kP<<<1, 64>>>(Wx, Wu, W1, b1, W2, b2);

    // Stage the duplicated weight table into the constant bank (D2D memcpy node).
    void* wd = nullptr;
    cudaGetSymbolAddress(&wd, g_wdup);
    cudaMemcpyToSymbolAsync(cw, wd, CW_N * sizeof(u64), 0,
                            cudaMemcpyDeviceToDevice, 0);

    dim3 gA(BB / 256, NCH);
    kA<<<gA, 256>>>(targets);
    kB<<<BB / 256, 256>>>();
    dim3 gC(QB / 128, NCH);
    kC<<<gC, 128>>>(inputs, targets, out);
}

// round 12
// speedup vs baseline: 1.2212x; 1.2212x over previous
#include <cuda_runtime.h>

// Problem constants (fixed by the reference).
#define TT   1024
#define BB   16384
#define CH   32          // steps per chunk
#define SQ   5           // log2(CH) squarings for Wx^CH
#define NCH  (TT / CH)   // 32 chunks
#define QB   (BB / 4)    // elements per "thread column" (4 adjacent per thread)

typedef unsigned long long u64;

static_assert((1 << SQ) == CH, "SQ must be log2(CH)");
static_assert(TT % CH == 0, "");

// Scratch.
__device__ float g_part[NCH * 6 * BB];   // zero-state per-chunk db partials
__device__ float g_ckpt[NCH * 6 * BB];   // true db at chunk entry
__device__ float g_m[CH * 6];            // m_s = Wx^s * Wu
__device__ float g_MC[36];               // Wx^CH

// Duplicated-pair weight table, staged by kP then copied to constant bank.
// Layout (u64 units):
//   rows i=0..5 at i*8: [Wx i0..i5 (pairs), Wu i (pair), pad]   (cw[7] = b2 pair)
//   rows j=0..19 at 48+j*16: [W1 j0..j11 (pairs), b1 j, W2 j, pad, pad]
#define CW_N 368
#define SW_ROWJ(j) (48 + (j) * 16)
__device__ u64 g_wdup[CW_N];
__constant__ __align__(16) u64 cw[CW_N];

// ---- f32x2 helpers (sm_100+ packed fp32 pipe) ----
__device__ __forceinline__ u64 pack2(float lo, float hi) {
    u64 r; asm("mov.b64 %0,{%1,%2};" : "=l"(r) : "f"(lo), "f"(hi)); return r;
}
__device__ __forceinline__ void unpack2(u64 v, float& lo, float& hi) {
    asm("mov.b64 {%0,%1},%2;" : "=f"(lo), "=f"(hi) : "l"(v));
}
__device__ __forceinline__ u64 fma2(u64 a, u64 b, u64 c) {
    u64 d; asm("fma.rn.f32x2 %0,%1,%2,%3;" : "=l"(d) : "l"(a), "l"(b), "l"(c)); return d;
}
__device__ __forceinline__ u64 mul2(u64 a, u64 b) {
    u64 d; asm("mul.rn.f32x2 %0,%1,%2;" : "=l"(d) : "l"(a), "l"(b)); return d;
}
__device__ __forceinline__ float tanh_(float x) {
    float y; asm("tanh.approx.f32 %0,%1;" : "=f"(y) : "f"(x)); return y;
}

// ============================================================
// Kernel P: precompute m_s = Wx^s Wu, Wx^CH, and the duplicated
// weight-pair table g_wdup. One block of 64 threads.
// ============================================================
__global__ void __launch_bounds__(64) kP(const float* __restrict__ Wx,
                                         const float* __restrict__ Wu,
                                         const float* __restrict__ W1,
                                         const float* __restrict__ b1,
                                         const float* __restrict__ W2,
                                         const float* __restrict__ b2) {
    __shared__ float sM[36], sm[6], sP[36], st[36];
    int t = threadIdx.x;
    if (t < 36) sM[t] = Wx[t];
    if (t < 6)  sm[t] = Wu[t];
    __syncthreads();

    for (int s = 0; s < CH; s++) {
        if (t < 6) g_m[s * 6 + t] = sm[t];
        __syncthreads();
        float nv = 0.f;
        if (t < 6) {
#pragma unroll
            for (int k = 0; k < 6; k++) nv = fmaf(sM[t * 6 + k], sm[k], nv);
        }
        __syncthreads();
        if (t < 6) sm[t] = nv;
        __syncthreads();
    }

    if (t < 36) sP[t] = sM[t];
    __syncthreads();
    for (int p = 0; p < SQ; p++) {
        if (t < 36) {
            int i = t / 6, j = t % 6;
            float a = 0.f;
#pragma unroll
            for (int k = 0; k < 6; k++) a = fmaf(sP[i * 6 + k], sP[k * 6 + j], a);
            st[t] = a;
        }
        __syncthreads();
        if (t < 36) sP[t] = st[t];
        __syncthreads();
    }
    if (t < 36) g_MC[t] = sP[t];

    // ---- duplicated-pair weight table ----
    if (t < 36) {
        float w = Wx[t];
        g_wdup[(t / 6) * 8 + (t % 6)] = pack2(w, w);
    } else if (t < 42) {
        int i = t - 36;
        float w = Wu[i];
        g_wdup[i * 8 + 6] = pack2(w, w);
        if (i > 0) g_wdup[i * 8 + 7] = 0ull;
    } else if (t < 62) {
        int j = t - 42;
        for (int i = 0; i < 12; i++) {
            float w = W1[j * 12 + i];
            g_wdup[SW_ROWJ(j) + i] = pack2(w, w);
        }
        float bj = b1[j];
        g_wdup[SW_ROWJ(j) + 12] = pack2(bj, bj);
        float w2j = W2[j];
        g_wdup[SW_ROWJ(j) + 13] = pack2(w2j, w2j);
        g_wdup[SW_ROWJ(j) + 14] = 0ull;
        g_wdup[SW_ROWJ(j) + 15] = 0ull;
    } else if (t == 62) {
        float bv = b2[0];
        g_wdup[7] = pack2(bv, bv);   // b2 pair in row-0 pad slot
    }
}

// ============================================================
// Kernel A: per-chunk zero-state db partials via convolution.
// ============================================================
__global__ void __launch_bounds__(256) kA(const float* __restrict__ targets) {
    __shared__ float sm[CH * 6];
    int tid = threadIdx.x;
    for (int i = tid; i < CH * 6; i += 256) sm[i] = g_m[i];
    __syncthreads();

    int b = blockIdx.x * 256 + tid;
    int c = blockIdx.y;
    int t0 = c * CH;

    float acc[6] = {0.f, 0.f, 0.f, 0.f, 0.f, 0.f};
#pragma unroll 8
    for (int s = 0; s < CH; s++) {
        int t = t0 + s;
        float u = 0.f;
        if (t > 0) u = targets[(size_t)(t - 1) * BB + b];
        const float* mm = &sm[(CH - 1 - s) * 6];
#pragma unroll
        for (int i = 0; i < 6; i++) acc[i] = fmaf(mm[i], u, acc[i]);
    }
#pragma unroll
    for (int i = 0; i < 6; i++)
        g_part[((size_t)c * 6 + i) * BB + b] = acc[i];
}

// ============================================================
// Kernel B: scan across chunks: db_in(c+1) = Wx^CH * db_in(c) + partial(c).
// ============================================================
__global__ void __launch_bounds__(256) kB() {
    __shared__ float sM[36];
    int tid = threadIdx.x;
    if (tid < 36) sM[tid] = g_MC[tid];
    __syncthreads();

    int b = blockIdx.x * 256 + tid;
    float v[6] = {0.f, 0.f, 0.f, 0.f, 0.f, 0.f};
#pragma unroll 1
    for (int c = 0; c < NCH; c++) {
#pragma unroll
        for (int i = 0; i < 6; i++)
            g_ckpt[((size_t)c * 6 + i) * BB + b] = v[i];
        float pr[6];
#pragma unroll
        for (int i = 0; i < 6; i++)
            pr[i] = g_part[((size_t)c * 6 + i) * BB + b];
        float nv[6];
#pragma unroll
        for (int i = 0; i < 6; i++) {
            float a = pr[i];
#pragma unroll
            for (int j = 0; j < 6; j++) a = fmaf(sM[i * 6 + j], v[j], a);
            nv[i] = a;
        }
#pragma unroll
        for (int i = 0; i < 6; i++) v[i] = nv[i];
    }
}

// ============================================================
// Kernel C: fused MLP. Weights from the constant bank (warp-uniform
// LDCU -> UR operands). FOUR ADJACENT batch elements per thread
// (4p..4p+3) as two f32x2 pairs: weight LDCU amortized over 2x math,
// and all gmem traffic becomes LDG.128/STG.128 (x: 6 loads, u: 1,
// out: 1 store). MLP processed 2 rows x 2 pairs = 4 concurrent chains
// (low UR + accumulator pressure; this is what R11's 8-chain version
// broke).
// ============================================================
__global__ void __launch_bounds__(128, 4) kC(const float* __restrict__ inputs,
                                             const float* __restrict__ targets,
                                             float* __restrict__ out) {
    const int tid = threadIdx.x;
    const int c   = blockIdx.y;
    const int p   = blockIdx.x * 128 + tid;   // 0..QB-1
    const int e0  = p * 4;                    // first of 4 adjacent elements

    // nA/nB: [0..5] = db (live state), [6..11] = packed x of current step
    u64 nA[12], nB[12];
    {
        const float4* ck = (const float4*)((const char*)g_ckpt +
                           ((size_t)c * 6 * BB + e0) * 4);
#pragma unroll
        for (int i = 0; i < 6; i++) {
            float4 v = *(const float4*)((const char*)ck + (size_t)i * BB * 4);
            nA[i] = pack2(v.x, v.y);
            nB[i] = pack2(v.z, v.w);
        }
    }

    const char* xp = (const char*)inputs  + ((size_t)c * CH * BB + e0) * 24;
    const char* tp = (const char*)targets + ((size_t)(c * CH - 1) * BB + e0) * 4;
    char*       op = (char*)out           + ((size_t)c * CH * BB + e0) * 4;

    const float b2v = ((const float*)cw)[14];   // low half of cw[7]

#pragma unroll 1
    for (int s = 0; s < CH; s++) {
        // ---- loads: 4 adjacent elements = 96 contiguous bytes = 6 x LDG.128 ----
        float4 f0 = ((const float4*)xp)[0];
        float4 f1 = ((const float4*)xp)[1];
        float4 f2 = ((const float4*)xp)[2];
        float4 f3 = ((const float4*)xp)[3];
        float4 f4 = ((const float4*)xp)[4];
        float4 f5 = ((const float4*)xp)[5];
        xp += (size_t)BB * 24;

        u64 uA, uB;
        if (c + s > 0) {                  // global step t = c*CH+s > 0
            float4 uv = *(const float4*)tp;
            uA = pack2(uv.x, uv.y);
            uB = pack2(uv.z, uv.w);
        } else {
            uA = 0ull; uB = 0ull;
        }
        tp += (size_t)BB * 4;

        // ---- db recurrence for both pairs (interleaved chains) ----
        u64 dA[6], dB[6];
#pragma unroll
        for (int i = 0; i < 6; i++) {
            const u64* r = &cw[i * 8];
            u64 a = mul2(r[6], uA);
            u64 b = mul2(r[6], uB);
            a = fma2(r[0], nA[0], a);  b = fma2(r[0], nB[0], b);
            a = fma2(r[1], nA[1], a);  b = fma2(r[1], nB[1], b);
            a = fma2(r[2], nA[2], a);  b = fma2(r[2], nB[2], b);
            a = fma2(r[3], nA[3], a);  b = fma2(r[3], nB[3], b);
            a = fma2(r[4], nA[4], a);  b = fma2(r[4], nB[4], b);
            a = fma2(r[5], nA[5], a);  b = fma2(r[5], nB[5], b);
            dA[i] = a;  dB[i] = b;
        }
#pragma unroll
        for (int i = 0; i < 6; i++) { nA[i] = dA[i]; nB[i] = dB[i]; }
        // elem0 = f0.x..f1.y, elem1 = f1.z..f2.w, elem2 = f3.x..f4.y, elem3 = f4.z..f5.w
        nA[6]  = pack2(f0.x, f1.z);   nB[6]  = pack2(f3.x, f4.z);
        nA[7]  = pack2(f0.y, f1.w);   nB[7]  = pack2(f3.y, f4.w);
        nA[8]  = pack2(f0.z, f2.x);   nB[8]  = pack2(f3.z, f5.x);
        nA[9]  = pack2(f0.w, f2.y);   nB[9]  = pack2(f3.w, f5.y);
        nA[10] = pack2(f1.x, f2.z);   nB[10] = pack2(f4.x, f5.z);
        nA[11] = pack2(f1.y, f2.w);   nB[11] = pack2(f4.y, f5.w);

        // ---- MLP: 20 hidden rows, 2 rows x 2 pairs = 4 concurrent chains ----
        float o0 = b2v, o1 = b2v, o2 = b2v, o3 = b2v;
#pragma unroll
        for (int jg = 0; jg < 10; jg++) {
            const int j0 = jg * 2;
            u64 a0 = cw[SW_ROWJ(j0 + 0) + 12], b0 = a0;
            u64 a1 = cw[SW_ROWJ(j0 + 1) + 12], b1 = a1;
#pragma unroll
            for (int k = 0; k < 12; k++) {
                u64 w0 = cw[SW_ROWJ(j0 + 0) + k];
                u64 w1 = cw[SW_ROWJ(j0 + 1) + k];
                a0 = fma2(w0, nA[k], a0);  b0 = fma2(w0, nB[k], b0);
                a1 = fma2(w1, nA[k], a1);  b1 = fma2(w1, nB[k], b1);
            }
            float lo, hi, w2s;
            w2s = ((const float*)cw)[(SW_ROWJ(j0 + 0) + 13) * 2];
            unpack2(a0, lo, hi); o0 = fmaf(w2s, tanh_(lo), o0); o1 = fmaf(w2s, tanh_(hi), o1);
            unpack2(b0, lo, hi); o2 = fmaf(w2s, tanh_(lo), o2); o3 = fmaf(w2s, tanh_(hi), o3);
            w2s = ((const float*)cw)[(SW_ROWJ(j0 + 1) + 13) * 2];
            unpack2(a1, lo, hi); o0 = fmaf(w2s, tanh_(lo), o0); o1 = fmaf(w2s, tanh_(hi), o1);
            unpack2(b1, lo, hi); o2 = fmaf(w2s, tanh_(lo), o2); o3 = fmaf(w2s, tanh_(hi), o3);
        }

        // ---- store: 4 adjacent elements, one STG.128 ----
        float4 ov = make_float4(o0, o1, o2, o3);
        *(float4*)op = ov;
        op += (size_t)BB * 4;
    }
}

// ============================================================
extern "C" void kernel_launch(void* const* d_in, const int* in_sizes, int n_in,
                              void* d_out, int out_size) {
    (void)in_sizes; (void)n_in; (void)out_size;
    const float* inputs  = (const float*)d_in[0];
    const float* targets = (const float*)d_in[1];
    const float* Wx      = (const float*)d_in[2];
    const float* Wu      = (const float*)d_in[3];
    const float* W1      = (const float*)d_in[4];
    const float* b1      = (const float*)d_in[5];
    const float* W2      = (const float*)d_in[6];
    const float* b2      = (const float*)d_in[7];
    float* out = (float*)d_out;

    kP<<<1, 64>>>(Wx, Wu, W1, b1, W2, b2);

    // Stage the duplicated weight table into the constant bank (D2D memcpy node).
    void* wd = nullptr;
    cudaGetSymbolAddress(&wd, g_wdup);
    cudaMemcpyToSymbolAsync(cw, wd, CW_N * sizeof(u64), 0,
                            cudaMemcpyDeviceToDevice, 0);

    dim3 gA(BB / 256, NCH);
    kA<<<gA, 256>>>(targets);
    kB<<<BB / 256, 256>>>();
    dim3 gC(QB / 128, NCH);
    kC<<<gC, 128>>>(inputs, targets, out);
}